// round 6
// baseline (speedup 1.0000x reference)
#include <cuda_runtime.h>
#include <cuda_bf16.h>
#include <cstdint>

// ============================================================================
// VQ quantizer: bf16 split mma.sync (m16n8k16, HMMA path — compiles on plain
// sm_103) prefilter + provably-exact fp32 argmin rescue.
// z [N,64] f32, codebook [512,64] f32.
// Outputs (concatenated f32): q_ste [N*64], loss [1], ids [N] (as float).
// ============================================================================

#define D        64
#define KCODES   512
#define MTILE    128
#define TPB      128
#define NSM_GRID 148
#define THR      2e-3f

// smem layout (byte offsets). Rows strided 144B => bank-conflict-free frags.
#define B_HI_OFF   0        // 512 x 144B  (bf16 hi codebook, k-contiguous)
#define B_LO_OFF   73728    // 512 x 144B
#define A_HI_OFF   147456   // 128 x 144B  (bf16 hi z-tile)
#define A_LO_OFF   165888   // 128 x 144B
#define C2H_OFF    184320   // 512 f32 (0.5*||c||^2)
#define KID_OFF    186368   // 128 int
#define SMEM_TOTAL 186880

__device__ double g_partial[4096];

// ---------------- helpers ----------------
__device__ __forceinline__ void mma_bf16(float* c, const uint32_t* a,
                                         uint32_t b0, uint32_t b1) {
    asm volatile(
        "mma.sync.aligned.m16n8k16.row.col.f32.bf16.bf16.f32 "
        "{%0,%1,%2,%3}, {%4,%5,%6,%7}, {%8,%9}, {%0,%1,%2,%3};"
        : "+f"(c[0]), "+f"(c[1]), "+f"(c[2]), "+f"(c[3])
        : "r"(a[0]), "r"(a[1]), "r"(a[2]), "r"(a[3]), "r"(b0), "r"(b1));
}

__device__ __forceinline__ void split2(float x, float y, uint32_t& hi, uint32_t& lo) {
    __nv_bfloat16 hx = __float2bfloat16_rn(x), hy = __float2bfloat16_rn(y);
    __nv_bfloat16 lx = __float2bfloat16_rn(x - __bfloat162float(hx));
    __nv_bfloat16 ly = __float2bfloat16_rn(y - __bfloat162float(hy));
    __nv_bfloat162 h2 = __halves2bfloat162(hx, hy);   // x -> low half (lower addr)
    __nv_bfloat162 l2 = __halves2bfloat162(lx, ly);
    hi = *(uint32_t*)&h2;
    lo = *(uint32_t*)&l2;
}

// split one 64-f32 row into bf16 hi/lo, plain write at 144B-strided row
__device__ __forceinline__ void store_row_split(char* smem, int hi_off, int lo_off,
                                                int rowbyte, const float4* v) {
    #pragma unroll
    for (int blk = 0; blk < 8; blk++) {
        float4 a = v[2 * blk], b = v[2 * blk + 1];
        uint4 hw, lw;
        split2(a.x, a.y, hw.x, lw.x);
        split2(a.z, a.w, hw.y, lw.y);
        split2(b.x, b.y, hw.z, lw.z);
        split2(b.z, b.w, hw.w, lw.w);
        *(uint4*)(smem + hi_off + rowbyte + blk * 16) = hw;
        *(uint4*)(smem + lo_off + rowbyte + blk * 16) = lw;
    }
}

// top-3 insert (descending)
__device__ __forceinline__ void ins3(float v, int k, float* tv, int* tk) {
    if (v > tv[2]) {
        if (v > tv[0])      { tv[2]=tv[1]; tk[2]=tk[1]; tv[1]=tv[0]; tk[1]=tk[0]; tv[0]=v; tk[0]=k; }
        else if (v > tv[1]) { tv[2]=tv[1]; tk[2]=tk[1]; tv[1]=v; tk[1]=k; }
        else                { tv[2]=v; tk[2]=k; }
    }
}

// EXACT scorer — replicates round-1 arithmetic (verified rel_err 0.0)
__device__ __forceinline__ float exact_d2(const float4* zr, float z2,
                                          const float* __restrict__ crow) {
    const float4* c4 = (const float4*)crow;
    float4 cv[16];
    #pragma unroll
    for (int i = 0; i < 16; i++) cv[i] = c4[i];
    float c2 = 0.f;
    #pragma unroll
    for (int i = 0; i < 16; i++) {
        c2 += cv[i].x * cv[i].x; c2 += cv[i].y * cv[i].y;
        c2 += cv[i].z * cv[i].z; c2 += cv[i].w * cv[i].w;
    }
    float a0 = 0.f, a1 = 0.f, a2 = 0.f, a3 = 0.f;
    #pragma unroll
    for (int i = 0; i < 16; i++) {
        a0 += zr[i].x * cv[i].x;
        a1 += zr[i].y * cv[i].y;
        a2 += zr[i].z * cv[i].z;
        a3 += zr[i].w * cv[i].w;
    }
    float dot = (a0 + a1) + (a2 + a3);
    return (z2 - 2.0f * dot) + c2;
}

__device__ __forceinline__ float z2_of(const float4* zr) {
    float z2 = 0.f;
    #pragma unroll
    for (int i = 0; i < 16; i++)
        z2 += zr[i].x * zr[i].x + zr[i].y * zr[i].y
            + zr[i].z * zr[i].z + zr[i].w * zr[i].w;
    return z2;
}

// ============================================================================
// Main kernel: persistent, 1 CTA/SM, 4 warps, M-tile 128 (2 m16-strips/warp)
// ============================================================================
__global__ __launch_bounds__(TPB, 1)
void vq_mma(const float* __restrict__ z, const float* __restrict__ cb,
            int N, float* __restrict__ q_out, float* __restrict__ ids_out)
{
    extern __shared__ char smem[];
    const int tid  = threadIdx.x;
    const int wid  = tid >> 5;
    const int lane = tid & 31;
    const int qr   = lane >> 2;   // 0..7
    const int qc   = lane & 3;    // 0..3

    float* c2h = (float*)(smem + C2H_OFF);
    int*   kid_smem = (int*)(smem + KID_OFF);

    // ---- stage codebook once: bf16 split + 0.5*||c||^2 ----
    for (int n = tid; n < KCODES; n += TPB) {
        float4 cv[16];
        const float4* c4 = (const float4*)(cb + (size_t)n * D);
        #pragma unroll
        for (int i = 0; i < 16; i++) cv[i] = c4[i];
        float s = 0.f;
        #pragma unroll
        for (int i = 0; i < 16; i++)
            s += cv[i].x * cv[i].x + cv[i].y * cv[i].y
               + cv[i].z * cv[i].z + cv[i].w * cv[i].w;
        c2h[n] = 0.5f * s;
        store_row_split(smem, B_HI_OFF, B_LO_OFF, n * 144, cv);
    }
    __syncthreads();

    const int ntiles = N / MTILE;
    double dsum = 0.0;

    for (int tile = blockIdx.x; tile < ntiles; tile += gridDim.x) {
        // ---- stage A: thread tid owns global row tile*128 + tid ----
        {
            float4 zr[16];
            const float4* zp = (const float4*)(z + (size_t)(tile * MTILE + tid) * D);
            #pragma unroll
            for (int i = 0; i < 16; i++) zr[i] = zp[i];
            store_row_split(smem, A_HI_OFF, A_LO_OFF, tid * 144, zr);
        }
        __syncthreads();

        // ---- per-thread top-3 for 4 row-slots ----
        // slot = strip*2 + half:  row_local = wid*32 + strip*16 + qr + half*8
        float tv[4][3];
        int   tk[4][3];
        #pragma unroll
        for (int s = 0; s < 4; s++) {
            tv[s][0] = tv[s][1] = tv[s][2] = -3.4e38f;
            tk[s][0] = tk[s][1] = tk[s][2] = 0;
        }

        for (int ch = 0; ch < 8; ch++) {          // 8 chunks of 64 codes
            float acc[2][8][4];
            #pragma unroll
            for (int s = 0; s < 2; s++)
                #pragma unroll
                for (int n8 = 0; n8 < 8; n8++)
                    #pragma unroll
                    for (int f = 0; f < 4; f++) acc[s][n8][f] = 0.f;

            #pragma unroll
            for (int ks = 0; ks < 4; ks++) {
                uint32_t aH[2][4], aL[2][4];
                const int kb = ks * 32 + qc * 4;
                #pragma unroll
                for (int s = 0; s < 2; s++) {
                    const int r0 = (wid * 32 + s * 16 + qr) * 144;
                    aH[s][0] = *(const uint32_t*)(smem + A_HI_OFF + r0 + kb);
                    aH[s][1] = *(const uint32_t*)(smem + A_HI_OFF + r0 + 8 * 144 + kb);
                    aH[s][2] = *(const uint32_t*)(smem + A_HI_OFF + r0 + kb + 16);
                    aH[s][3] = *(const uint32_t*)(smem + A_HI_OFF + r0 + 8 * 144 + kb + 16);
                    aL[s][0] = *(const uint32_t*)(smem + A_LO_OFF + r0 + kb);
                    aL[s][1] = *(const uint32_t*)(smem + A_LO_OFF + r0 + 8 * 144 + kb);
                    aL[s][2] = *(const uint32_t*)(smem + A_LO_OFF + r0 + kb + 16);
                    aL[s][3] = *(const uint32_t*)(smem + A_LO_OFF + r0 + 8 * 144 + kb + 16);
                }
                #pragma unroll
                for (int n8 = 0; n8 < 8; n8++) {
                    const int cbyte = (ch * 64 + n8 * 8 + qr) * 144 + kb;
                    uint32_t bh0 = *(const uint32_t*)(smem + B_HI_OFF + cbyte);
                    uint32_t bh1 = *(const uint32_t*)(smem + B_HI_OFF + cbyte + 16);
                    uint32_t bl0 = *(const uint32_t*)(smem + B_LO_OFF + cbyte);
                    uint32_t bl1 = *(const uint32_t*)(smem + B_LO_OFF + cbyte + 16);
                    #pragma unroll
                    for (int s = 0; s < 2; s++) {
                        mma_bf16(acc[s][n8], aH[s], bh0, bh1);  // zh*ch
                        mma_bf16(acc[s][n8], aH[s], bl0, bl1);  // zh*cl
                        mma_bf16(acc[s][n8], aL[s], bh0, bh1);  // zl*ch
                    }
                }
            }

            // rank: v = dot - 0.5*||c||^2, update top-3 per slot
            #pragma unroll
            for (int n8 = 0; n8 < 8; n8++) {
                const int col0 = ch * 64 + n8 * 8 + qc * 2;
                const float h0 = c2h[col0], h1 = c2h[col0 + 1];
                #pragma unroll
                for (int s = 0; s < 2; s++) {
                    ins3(acc[s][n8][0] - h0, col0,     tv[s*2],   tk[s*2]);
                    ins3(acc[s][n8][1] - h1, col0 + 1, tv[s*2],   tk[s*2]);
                    ins3(acc[s][n8][2] - h0, col0,     tv[s*2+1], tk[s*2+1]);
                    ins3(acc[s][n8][3] - h1, col0 + 1, tv[s*2+1], tk[s*2+1]);
                }
            }
        }

        // ---- quad merge (bfly xor 1, 2) -> global top-3 per slot ----
        float loc3[4];
        #pragma unroll
        for (int s = 0; s < 4; s++) loc3[s] = tv[s][2];

        #pragma unroll
        for (int off = 1; off <= 2; off <<= 1) {
            #pragma unroll
            for (int s = 0; s < 4; s++) {
                float sv0 = tv[s][0], sv1 = tv[s][1], sv2 = tv[s][2];
                int   sk0 = tk[s][0], sk1 = tk[s][1], sk2 = tk[s][2];
                float ov0 = __shfl_xor_sync(0xffffffffu, sv0, off);
                float ov1 = __shfl_xor_sync(0xffffffffu, sv1, off);
                float ov2 = __shfl_xor_sync(0xffffffffu, sv2, off);
                int   ok0 = __shfl_xor_sync(0xffffffffu, sk0, off);
                int   ok1 = __shfl_xor_sync(0xffffffffu, sk1, off);
                int   ok2 = __shfl_xor_sync(0xffffffffu, sk2, off);
                ins3(ov0, ok0, tv[s], tk[s]);
                ins3(ov1, ok1, tv[s], tk[s]);
                ins3(ov2, ok2, tv[s], tk[s]);
            }
        }

        // ---- coverage check: any lane's local 3rd-best within THR of b1? ----
        unsigned unsafe_mask[4];
        #pragma unroll
        for (int s = 0; s < 4; s++) {
            unsigned bal = __ballot_sync(0xffffffffu, loc3[s] >= tv[s][0] - THR);
            unsafe_mask[s] = (bal >> (lane & ~3)) & 0xFu;
        }

        // ---- finalize: lane qc handles slot qc of its quad ----
        {
            const int s = qc;
            const int row_local = wid * 32 + (s >> 1) * 16 + qr + (s & 1) * 8;
            const int grow = tile * MTILE + row_local;
            const float b1 = tv[s][0];
            const float thr = b1 - THR;
            int kid;

            if (unsafe_mask[s]) {
                // rare: full exact scan
                float4 zr[16];
                const float4* zp = (const float4*)(z + (size_t)grow * D);
                #pragma unroll
                for (int i = 0; i < 16; i++) zr[i] = zp[i];
                const float z2 = z2_of(zr);
                float best = 3.402823466e38f; kid = 0;
                for (int k = 0; k < KCODES; k++) {
                    float d = exact_d2(zr, z2, cb + (size_t)k * D);
                    if (d < best) { best = d; kid = k; }
                }
            } else {
                int ck[3]; int nc = 1;
                ck[0] = tk[s][0];
                if (tv[s][1] >= thr) ck[nc++] = tk[s][1];
                if (tv[s][2] >= thr) ck[nc++] = tk[s][2];
                if (nc == 1) {
                    kid = ck[0];                       // margin proves exact winner
                } else {
                    if (nc >= 2 && ck[0] > ck[1]) { int t = ck[0]; ck[0] = ck[1]; ck[1] = t; }
                    if (nc == 3) {
                        if (ck[1] > ck[2]) { int t = ck[1]; ck[1] = ck[2]; ck[2] = t; }
                        if (ck[0] > ck[1]) { int t = ck[0]; ck[0] = ck[1]; ck[1] = t; }
                    }
                    float4 zr[16];
                    const float4* zp = (const float4*)(z + (size_t)grow * D);
                    #pragma unroll
                    for (int i = 0; i < 16; i++) zr[i] = zp[i];
                    const float z2 = z2_of(zr);
                    float best = 3.402823466e38f; kid = ck[0];
                    for (int i = 0; i < nc; i++) {     // ascending k, strict <
                        float d = exact_d2(zr, z2, cb + (size_t)ck[i] * D);
                        if (d < best) { best = d; kid = ck[i]; }
                    }
                }
            }
            kid_smem[row_local] = kid;
        }
        __syncthreads();

        // ---- owner epilogue: thread tid finishes row tile*128+tid ----
        {
            const int grow = tile * MTILE + tid;
            const int kid = kid_smem[tid];
            float4 zr[16];
            const float4* zp = (const float4*)(z + (size_t)grow * D);
            #pragma unroll
            for (int i = 0; i < 16; i++) zr[i] = zp[i];
            const float4* q4 = (const float4*)(cb + (size_t)kid * D);
            float4* qo = (float4*)(q_out + (size_t)grow * D);
            float lsum = 0.f;
            #pragma unroll
            for (int i = 0; i < 16; i++) {
                float4 cv = q4[i];
                float4 zv = zr[i];
                float dx = zv.x - cv.x, dy = zv.y - cv.y;
                float dz = zv.z - cv.z, dw = zv.w - cv.w;
                lsum += dx * dx + dy * dy + dz * dz + dw * dw;
                float4 o;
                o.x = zv.x + (cv.x - zv.x);   // fl(z + fl(q - z)), reference STE
                o.y = zv.y + (cv.y - zv.y);
                o.z = zv.z + (cv.z - zv.z);
                o.w = zv.w + (cv.w - zv.w);
                qo[i] = o;
            }
            if (ids_out) ids_out[grow] = (float)kid;
            dsum += (double)lsum;
        }
        __syncthreads();
    }

    // ---- deterministic per-CTA loss reduction ----
    double* red = (double*)(smem + A_HI_OFF);
    red[tid] = dsum;
    __syncthreads();
    if (tid == 0) {
        double s = 0.0;
        for (int i = 0; i < TPB; i++) s += red[i];
        g_partial[blockIdx.x] = s;
    }
}

// ============================================================================
// Generic fallback (round-2 kernel) for unexpected shapes
// ============================================================================
#define FTPB 256
#define ROW_PAD 68
__global__ __launch_bounds__(FTPB) void vq_ref(
    const float* __restrict__ z, const float* __restrict__ cb,
    int N, int K, float* __restrict__ q_out, float* __restrict__ ids_out)
{
    extern __shared__ float fsm[];
    float* cbs = fsm;
    float* c2  = fsm + (size_t)K * ROW_PAD;
    const int tid = threadIdx.x;
    const float4* cb4 = (const float4*)cb;
    const int nvec = K * (D / 4);
    for (int idx = tid; idx < nvec; idx += FTPB) {
        int k = idx >> 4, c = idx & 15;
        *(float4*)&cbs[k * ROW_PAD + c * 4] = cb4[idx];
    }
    __syncthreads();
    for (int k = tid; k < K; k += FTPB) {
        const float* r = &cbs[k * ROW_PAD];
        float s = 0.f;
        #pragma unroll
        for (int i = 0; i < D; i++) s += r[i] * r[i];
        c2[k] = s;
    }
    __syncthreads();
    const int row = blockIdx.x * FTPB + tid;
    float lsum = 0.f;
    if (row < N) {
        float4 zr[16];
        const float4* zp = (const float4*)(z + (size_t)row * D);
        #pragma unroll
        for (int i = 0; i < 16; i++) zr[i] = zp[i];
        float z2 = 0.f;
        #pragma unroll
        for (int i = 0; i < 16; i++)
            z2 += zr[i].x * zr[i].x + zr[i].y * zr[i].y
                + zr[i].z * zr[i].z + zr[i].w * zr[i].w;
        float best = 3.402823466e38f; int bid = 0;
        for (int k = 0; k < K; k++) {
            const float4* crow = (const float4*)&cbs[k * ROW_PAD];
            float a0 = 0.f, a1 = 0.f, a2 = 0.f, a3 = 0.f;
            #pragma unroll
            for (int i = 0; i < 16; i++) {
                float4 cv = crow[i];
                a0 += zr[i].x * cv.x; a1 += zr[i].y * cv.y;
                a2 += zr[i].z * cv.z; a3 += zr[i].w * cv.w;
            }
            float dot = (a0 + a1) + (a2 + a3);
            float d = (z2 - 2.0f * dot) + c2[k];
            if (d < best) { best = d; bid = k; }
        }
        const float4* crow = (const float4*)&cbs[bid * ROW_PAD];
        float4* qo = (float4*)(q_out + (size_t)row * D);
        #pragma unroll
        for (int i = 0; i < 16; i++) {
            float4 cv = crow[i];
            float4 zv = zr[i];
            float dx = zv.x - cv.x, dy = zv.y - cv.y;
            float dz = zv.z - cv.z, dw = zv.w - cv.w;
            lsum += dx * dx + dy * dy + dz * dz + dw * dw;
            float4 o;
            o.x = zv.x + (cv.x - zv.x); o.y = zv.y + (cv.y - zv.y);
            o.z = zv.z + (cv.z - zv.z); o.w = zv.w + (cv.w - zv.w);
            qo[i] = o;
        }
        if (ids_out) ids_out[row] = (float)bid;
    }
    #pragma unroll
    for (int off = 16; off; off >>= 1)
        lsum += __shfl_down_sync(0xffffffffu, lsum, off);
    __shared__ double wp[FTPB / 32];
    if ((tid & 31) == 0) wp[tid >> 5] = (double)lsum;
    __syncthreads();
    if (tid == 0) {
        double s = 0.0;
        #pragma unroll
        for (int w = 0; w < FTPB / 32; w++) s += wp[w];
        g_partial[blockIdx.x] = s;
    }
}

__global__ void vq_finalize(int nblocks, double inv_total, float* loss_out)
{
    __shared__ double sp[256];
    const int tid = threadIdx.x;
    double s = 0.0;
    for (int i = tid; i < nblocks; i += 256) s += g_partial[i];
    sp[tid] = s;
    __syncthreads();
    for (int off = 128; off; off >>= 1) {
        if (tid < off) sp[tid] += sp[tid + off];
        __syncthreads();
    }
    if (tid == 0) {
        double mean = sp[0] * inv_total;
        loss_out[0] = (float)(mean + 0.25 * mean);
    }
}

extern "C" void kernel_launch(void* const* d_in, const int* in_sizes, int n_in,
                              void* d_out, int out_size)
{
    const float* z  = (const float*)d_in[0];
    const float* cb = (const float*)d_in[1];
    const int N = in_sizes[0] / D;
    const int K = in_sizes[1] / D;

    float* out = (float*)d_out;
    float* q_out    = out;
    float* loss_ptr = nullptr;
    float* ids_ptr  = nullptr;
    const long base = (long)N * D;
    if ((long)out_size >= base + 1 + N) { loss_ptr = out + base; ids_ptr = out + base + 1; }
    else if ((long)out_size == base + N) { ids_ptr = out + base; }
    else if ((long)out_size == base + 1) { loss_ptr = out + base; }

    int nblocks;
    if (K == KCODES && (N % MTILE) == 0 && N > 0) {
        const int ntiles = N / MTILE;
        nblocks = ntiles < NSM_GRID ? ntiles : NSM_GRID;
        cudaFuncSetAttribute(vq_mma, cudaFuncAttributeMaxDynamicSharedMemorySize, SMEM_TOTAL);
        vq_mma<<<nblocks, TPB, SMEM_TOTAL>>>(z, cb, N, q_out, ids_ptr);
    } else {
        const size_t smem_bytes = ((size_t)K * ROW_PAD + K) * sizeof(float);
        cudaFuncSetAttribute(vq_ref, cudaFuncAttributeMaxDynamicSharedMemorySize, (int)smem_bytes);
        nblocks = (N + FTPB - 1) / FTPB;
        vq_ref<<<nblocks, FTPB, smem_bytes>>>(z, cb, N, K, q_out, ids_ptr);
    }

    if (loss_ptr) {
        double inv_total = 1.0 / ((double)N * (double)D);
        vq_finalize<<<1, 256>>>(nblocks, inv_total, loss_ptr);
    }
}

// round 7
// speedup vs baseline: 4.3369x; 4.3369x over previous
#include <cuda_runtime.h>
#include <cuda_fp16.h>
#include <cuda_bf16.h>
#include <cstdint>

// ============================================================================
// VQ quantizer: single-pass fp16 mma.sync prefilter (per-row rigorous error
// bound) + provably-exact fp32 argmin rescue.
// z [N,64] f32, codebook [512,64] f32.
// Outputs (concatenated f32): q_ste [N*64], loss [1], ids [N] (as float).
// ============================================================================

#define D        64
#define KCODES   512
#define MTILE    128
#define TPB      256
#define GRID_MAX 296   // 2 CTAs/SM x 148 SMs

// smem layout (byte offsets); fp16 rows strided 144B => conflict-free frags
#define B_OFF      0        // 512 x 144B fp16 codebook (k-contiguous rows)
#define A_OFF      73728    // 128 x 144B fp16 z tile
#define C2H_OFF    92160    // 512 f32: 0.5*||c||^2
#define Z2S_OFF    94208    // 128 f32: approx ||z||^2 per tile row
#define KID_OFF    94720    // 128 int
#define CN_OFF     95232    // 1 f32: max ||c||
#define SMEM_TOTAL 95744

__device__ double g_partial[4096];

// ---------------- helpers ----------------
__device__ __forceinline__ void mma_fp16(float* c, const uint32_t* a,
                                         uint32_t b0, uint32_t b1) {
    asm volatile(
        "mma.sync.aligned.m16n8k16.row.col.f32.f16.f16.f32 "
        "{%0,%1,%2,%3}, {%4,%5,%6,%7}, {%8,%9}, {%0,%1,%2,%3};"
        : "+f"(c[0]), "+f"(c[1]), "+f"(c[2]), "+f"(c[3])
        : "r"(a[0]), "r"(a[1]), "r"(a[2]), "r"(a[3]), "r"(b0), "r"(b1));
}

// top-3 insert (descending)
__device__ __forceinline__ void ins3(float v, int k, float* tv, int* tk) {
    if (v > tv[2]) {
        if (v > tv[0])      { tv[2]=tv[1]; tk[2]=tk[1]; tv[1]=tv[0]; tk[1]=tk[0]; tv[0]=v; tk[0]=k; }
        else if (v > tv[1]) { tv[2]=tv[1]; tk[2]=tk[1]; tv[1]=v; tk[1]=k; }
        else                { tv[2]=v; tk[2]=k; }
    }
}

// EXACT scorer — replicates round-1 arithmetic (verified rel_err 0.0)
__device__ __forceinline__ float exact_d2(const float4* zr, float z2,
                                          const float* __restrict__ crow) {
    const float4* c4 = (const float4*)crow;
    float4 cv[16];
    #pragma unroll
    for (int i = 0; i < 16; i++) cv[i] = c4[i];
    float c2 = 0.f;
    #pragma unroll
    for (int i = 0; i < 16; i++) {
        c2 += cv[i].x * cv[i].x; c2 += cv[i].y * cv[i].y;
        c2 += cv[i].z * cv[i].z; c2 += cv[i].w * cv[i].w;
    }
    float a0 = 0.f, a1 = 0.f, a2 = 0.f, a3 = 0.f;
    #pragma unroll
    for (int i = 0; i < 16; i++) {
        a0 += zr[i].x * cv[i].x;
        a1 += zr[i].y * cv[i].y;
        a2 += zr[i].z * cv[i].z;
        a3 += zr[i].w * cv[i].w;
    }
    float dot = (a0 + a1) + (a2 + a3);
    return (z2 - 2.0f * dot) + c2;
}

__device__ __forceinline__ float z2_of(const float4* zr) {
    float z2 = 0.f;
    #pragma unroll
    for (int i = 0; i < 16; i++)
        z2 += zr[i].x * zr[i].x + zr[i].y * zr[i].y
            + zr[i].z * zr[i].z + zr[i].w * zr[i].w;
    return z2;
}

// convert 64 f32 -> fp16 row (144B stride), return sum of squares (approx ok)
__device__ __forceinline__ float stage_row_fp16(char* dst, const float4* v) {
    float s = 0.f;
    #pragma unroll
    for (int i = 0; i < 16; i++) {
        float4 a = v[i];
        s += a.x * a.x + a.y * a.y + a.z * a.z + a.w * a.w;
        __half2 h0 = __halves2half2(__float2half_rn(a.x), __float2half_rn(a.y));
        __half2 h1 = __halves2half2(__float2half_rn(a.z), __float2half_rn(a.w));
        uint2 w;
        w.x = *(uint32_t*)&h0;
        w.y = *(uint32_t*)&h1;
        *(uint2*)(dst + i * 8) = w;
    }
    return s;
}

// ============================================================================
// Main kernel: persistent, 2 CTAs/SM, 8 warps, M-tile 128 (1 m16 strip/warp)
// ============================================================================
__global__ __launch_bounds__(TPB, 2)
void vq_mma(const float* __restrict__ z, const float* __restrict__ cb,
            int N, float* __restrict__ q_out, float* __restrict__ ids_out)
{
    extern __shared__ char smem[];
    const int tid  = threadIdx.x;
    const int wid  = tid >> 5;
    const int lane = tid & 31;
    const int qr   = lane >> 2;   // 0..7
    const int qc   = lane & 3;    // 0..3

    float* c2h  = (float*)(smem + C2H_OFF);
    float* z2s  = (float*)(smem + Z2S_OFF);
    int*   kidS = (int*)(smem + KID_OFF);
    float* cnp  = (float*)(smem + CN_OFF);

    // ---- stage codebook once: fp16 rows + 0.5*||c||^2 ----
    for (int n = tid; n < KCODES; n += TPB) {
        float4 cv[16];
        const float4* c4 = (const float4*)(cb + (size_t)n * D);
        #pragma unroll
        for (int i = 0; i < 16; i++) cv[i] = c4[i];
        float s = stage_row_fp16(smem + B_OFF + n * 144, cv);
        c2h[n] = 0.5f * s;
    }
    __syncthreads();
    if (tid < 32) {
        float m = 0.f;
        for (int i = tid; i < KCODES; i += 32) m = fmaxf(m, c2h[i]);
        #pragma unroll
        for (int off = 16; off; off >>= 1)
            m = fmaxf(m, __shfl_xor_sync(0xffffffffu, m, off));
        if (tid == 0) *cnp = sqrtf(2.0f * m);
    }
    __syncthreads();
    const float CNMAX = *cnp;

    const int ntiles = N / MTILE;
    double dsum = 0.0;

    for (int tile = blockIdx.x; tile < ntiles; tile += gridDim.x) {
        // ---- stage A tile: threads 0..127 convert one row each ----
        if (tid < MTILE) {
            float4 zr[16];
            const float4* zp = (const float4*)(z + (size_t)(tile * MTILE + tid) * D);
            #pragma unroll
            for (int i = 0; i < 16; i++) zr[i] = zp[i];
            z2s[tid] = stage_row_fp16(smem + A_OFF + tid * 144, zr);
        }
        __syncthreads();

        // ---- A fragments (hoisted; strip rows wid*16+qr, +8) ----
        uint32_t afr[4][4];
        {
            const int r0 = (wid * 16 + qr) * 144;
            #pragma unroll
            for (int ks = 0; ks < 4; ks++) {
                const int kb = ks * 32 + qc * 4;
                afr[ks][0] = *(const uint32_t*)(smem + A_OFF + r0 + kb);
                afr[ks][1] = *(const uint32_t*)(smem + A_OFF + r0 + 8 * 144 + kb);
                afr[ks][2] = *(const uint32_t*)(smem + A_OFF + r0 + kb + 16);
                afr[ks][3] = *(const uint32_t*)(smem + A_OFF + r0 + 8 * 144 + kb + 16);
            }
        }

        // ---- MMA + per-thread top-3 for 2 row-slots ----
        float tv[2][3];
        int   tk[2][3];
        #pragma unroll
        for (int s = 0; s < 2; s++) {
            tv[s][0] = tv[s][1] = tv[s][2] = -3.4e38f;
            tk[s][0] = tk[s][1] = tk[s][2] = 0;
        }

        for (int ch = 0; ch < 8; ch++) {       // 8 chunks of 64 codes
            float acc[8][4];
            #pragma unroll
            for (int n8 = 0; n8 < 8; n8++)
                #pragma unroll
                for (int f = 0; f < 4; f++) acc[n8][f] = 0.f;

            #pragma unroll
            for (int ks = 0; ks < 4; ks++) {
                const int kb = ks * 32 + qc * 4;
                #pragma unroll
                for (int n8 = 0; n8 < 8; n8++) {
                    const int cbyte = (ch * 64 + n8 * 8 + qr) * 144 + kb;
                    uint32_t b0 = *(const uint32_t*)(smem + B_OFF + cbyte);
                    uint32_t b1 = *(const uint32_t*)(smem + B_OFF + cbyte + 16);
                    mma_fp16(acc[n8], afr[ks], b0, b1);
                }
            }

            #pragma unroll
            for (int n8 = 0; n8 < 8; n8++) {
                const int col0 = ch * 64 + n8 * 8 + qc * 2;
                const float h0 = c2h[col0], h1 = c2h[col0 + 1];
                ins3(acc[n8][0] - h0, col0,     tv[0], tk[0]);
                ins3(acc[n8][1] - h1, col0 + 1, tv[0], tk[0]);
                ins3(acc[n8][2] - h0, col0,     tv[1], tk[1]);
                ins3(acc[n8][3] - h1, col0 + 1, tv[1], tk[1]);
            }
        }

        const float loc3_0 = tv[0][2];
        const float loc3_1 = tv[1][2];

        // ---- quad merge (xor 1, 2) -> global top-3 per slot ----
        #pragma unroll
        for (int off = 1; off <= 2; off <<= 1) {
            #pragma unroll
            for (int s = 0; s < 2; s++) {
                float sv0 = tv[s][0], sv1 = tv[s][1], sv2 = tv[s][2];
                int   sk0 = tk[s][0], sk1 = tk[s][1], sk2 = tk[s][2];
                float ov0 = __shfl_xor_sync(0xffffffffu, sv0, off);
                float ov1 = __shfl_xor_sync(0xffffffffu, sv1, off);
                float ov2 = __shfl_xor_sync(0xffffffffu, sv2, off);
                int   ok0 = __shfl_xor_sync(0xffffffffu, sk0, off);
                int   ok1 = __shfl_xor_sync(0xffffffffu, sk1, off);
                int   ok2 = __shfl_xor_sync(0xffffffffu, sk2, off);
                ins3(ov0, ok0, tv[s], tk[s]);
                ins3(ov1, ok1, tv[s], tk[s]);
                ins3(ov2, ok2, tv[s], tk[s]);
            }
        }

        // ---- per-row rigorous threshold: 2e <= 2^-9 * ||z|| * ||c||max ----
        const int r0 = wid * 16 + qr;
        const float thr0 = sqrtf(z2s[r0])     * CNMAX * 0.001953125f + 5e-4f;
        const float thr1 = sqrtf(z2s[r0 + 8]) * CNMAX * 0.001953125f + 5e-4f;

        unsigned bal0 = __ballot_sync(0xffffffffu, loc3_0 >= tv[0][0] - thr0);
        unsigned bal1 = __ballot_sync(0xffffffffu, loc3_1 >= tv[1][0] - thr1);
        const unsigned qsh = lane & ~3;
        const bool u0 = ((bal0 >> qsh) & 0xFu) != 0;
        const bool u1 = ((bal1 >> qsh) & 0xFu) != 0;

        // ---- finalize: lane qc=0 -> slot 0, qc=1 -> slot 1 ----
        const bool mine = (qc < 2);
        const int  myrow = r0 + qc * 8;                 // valid when mine
        const bool my_unsafe = mine && (qc == 0 ? u0 : u1);
        int kid = 0;

        if (mine && !my_unsafe) {
            float b0v, b1v, b2v, myTHR;
            int   k0v, k1v, k2v;
            if (qc == 0) { b0v=tv[0][0]; b1v=tv[0][1]; b2v=tv[0][2];
                           k0v=tk[0][0]; k1v=tk[0][1]; k2v=tk[0][2]; myTHR=thr0; }
            else         { b0v=tv[1][0]; b1v=tv[1][1]; b2v=tv[1][2];
                           k0v=tk[1][0]; k1v=tk[1][1]; k2v=tk[1][2]; myTHR=thr1; }
            const float thrv = b0v - myTHR;
            int ck[3]; int nc = 1;
            ck[0] = k0v;
            if (b1v >= thrv) ck[nc++] = k1v;
            if (b2v >= thrv) ck[nc++] = k2v;
            if (nc == 1) {
                kid = ck[0];                            // margin proves winner
            } else {
                if (ck[0] > ck[1]) { int t = ck[0]; ck[0] = ck[1]; ck[1] = t; }
                if (nc == 3) {
                    if (ck[1] > ck[2]) { int t = ck[1]; ck[1] = ck[2]; ck[2] = t; }
                    if (ck[0] > ck[1]) { int t = ck[0]; ck[0] = ck[1]; ck[1] = t; }
                }
                const int grow = tile * MTILE + myrow;
                float4 zr[16];
                const float4* zp = (const float4*)(z + (size_t)grow * D);
                #pragma unroll
                for (int i = 0; i < 16; i++) zr[i] = zp[i];
                const float z2 = z2_of(zr);
                float best = 3.402823466e38f; kid = ck[0];
                for (int i = 0; i < nc; i++) {          // ascending k, strict <
                    float d = exact_d2(zr, z2, cb + (size_t)ck[i] * D);
                    if (d < best) { best = d; kid = ck[i]; }
                }
            }
        }

        // ---- warp-cooperative exact scan for unsafe rows (rare) ----
        unsigned need = __ballot_sync(0xffffffffu, my_unsafe);
        while (need) {
            const int src = __ffs(need) - 1;
            need &= need - 1;
            const int rl = __shfl_sync(0xffffffffu, myrow, src);
            const int grow = tile * MTILE + rl;
            float4 zr[16];
            const float4* zp = (const float4*)(z + (size_t)grow * D);
            #pragma unroll
            for (int i = 0; i < 16; i++) zr[i] = zp[i];
            const float z2 = z2_of(zr);
            float best = 3.402823466e38f; int bk = KCODES;
            for (int k = lane; k < KCODES; k += 32) {   // lane-ascending, strict <
                float d = exact_d2(zr, z2, cb + (size_t)k * D);
                if (d < best) { best = d; bk = k; }
            }
            #pragma unroll
            for (int off = 16; off; off >>= 1) {
                float ob = __shfl_xor_sync(0xffffffffu, best, off);
                int   obk = __shfl_xor_sync(0xffffffffu, bk, off);
                if (ob < best || (ob == best && obk < bk)) { best = ob; bk = obk; }
            }
            if (lane == src) kid = bk;
        }

        if (mine) kidS[myrow] = kid;
        __syncthreads();

        // ---- epilogue: threads 0..127, row tid ----
        if (tid < MTILE) {
            const int grow = tile * MTILE + tid;
            const int k = kidS[tid];
            float4 zr[16];
            const float4* zp = (const float4*)(z + (size_t)grow * D);
            #pragma unroll
            for (int i = 0; i < 16; i++) zr[i] = zp[i];
            const float4* q4 = (const float4*)(cb + (size_t)k * D);
            float4* qo = (float4*)(q_out + (size_t)grow * D);
            float lsum = 0.f;
            #pragma unroll
            for (int i = 0; i < 16; i++) {
                float4 cv = q4[i];
                float4 zv = zr[i];
                float dx = zv.x - cv.x, dy = zv.y - cv.y;
                float dz = zv.z - cv.z, dw = zv.w - cv.w;
                lsum += dx * dx + dy * dy + dz * dz + dw * dw;
                float4 o;
                o.x = zv.x + (cv.x - zv.x);   // fl(z + fl(q - z)), reference STE
                o.y = zv.y + (cv.y - zv.y);
                o.z = zv.z + (cv.z - zv.z);
                o.w = zv.w + (cv.w - zv.w);
                qo[i] = o;
            }
            if (ids_out) ids_out[grow] = (float)k;
            dsum += (double)lsum;
        }
        __syncthreads();
    }

    // ---- deterministic per-CTA loss reduction ----
    double* red = (double*)(smem + B_OFF);   // codebook region reusable now
    red[tid] = dsum;
    __syncthreads();
    if (tid == 0) {
        double s = 0.0;
        for (int i = 0; i < TPB; i++) s += red[i];
        g_partial[blockIdx.x] = s;
    }
}

// ============================================================================
// Generic fallback (round-2 kernel) for unexpected shapes
// ============================================================================
#define FTPB 256
#define ROW_PAD 68
__global__ __launch_bounds__(FTPB) void vq_ref(
    const float* __restrict__ z, const float* __restrict__ cb,
    int N, int K, float* __restrict__ q_out, float* __restrict__ ids_out)
{
    extern __shared__ float fsm[];
    float* cbs = fsm;
    float* c2  = fsm + (size_t)K * ROW_PAD;
    const int tid = threadIdx.x;
    const float4* cb4 = (const float4*)cb;
    const int nvec = K * (D / 4);
    for (int idx = tid; idx < nvec; idx += FTPB) {
        int k = idx >> 4, c = idx & 15;
        *(float4*)&cbs[k * ROW_PAD + c * 4] = cb4[idx];
    }
    __syncthreads();
    for (int k = tid; k < K; k += FTPB) {
        const float* r = &cbs[k * ROW_PAD];
        float s = 0.f;
        #pragma unroll
        for (int i = 0; i < D; i++) s += r[i] * r[i];
        c2[k] = s;
    }
    __syncthreads();
    const int row = blockIdx.x * FTPB + tid;
    float lsum = 0.f;
    if (row < N) {
        float4 zr[16];
        const float4* zp = (const float4*)(z + (size_t)row * D);
        #pragma unroll
        for (int i = 0; i < 16; i++) zr[i] = zp[i];
        float z2 = 0.f;
        #pragma unroll
        for (int i = 0; i < 16; i++)
            z2 += zr[i].x * zr[i].x + zr[i].y * zr[i].y
                + zr[i].z * zr[i].z + zr[i].w * zr[i].w;
        float best = 3.402823466e38f; int bid = 0;
        for (int k = 0; k < K; k++) {
            const float4* crow = (const float4*)&cbs[k * ROW_PAD];
            float a0 = 0.f, a1 = 0.f, a2 = 0.f, a3 = 0.f;
            #pragma unroll
            for (int i = 0; i < 16; i++) {
                float4 cv = crow[i];
                a0 += zr[i].x * cv.x; a1 += zr[i].y * cv.y;
                a2 += zr[i].z * cv.z; a3 += zr[i].w * cv.w;
            }
            float dot = (a0 + a1) + (a2 + a3);
            float d = (z2 - 2.0f * dot) + c2[k];
            if (d < best) { best = d; bid = k; }
        }
        const float4* crow = (const float4*)&cbs[bid * ROW_PAD];
        float4* qo = (float4*)(q_out + (size_t)row * D);
        #pragma unroll
        for (int i = 0; i < 16; i++) {
            float4 cv = crow[i];
            float4 zv = zr[i];
            float dx = zv.x - cv.x, dy = zv.y - cv.y;
            float dz = zv.z - cv.z, dw = zv.w - cv.w;
            lsum += dx * dx + dy * dy + dz * dz + dw * dw;
            float4 o;
            o.x = zv.x + (cv.x - zv.x); o.y = zv.y + (cv.y - zv.y);
            o.z = zv.z + (cv.z - zv.z); o.w = zv.w + (cv.w - zv.w);
            qo[i] = o;
        }
        if (ids_out) ids_out[row] = (float)bid;
    }
    #pragma unroll
    for (int off = 16; off; off >>= 1)
        lsum += __shfl_down_sync(0xffffffffu, lsum, off);
    __shared__ double wp[FTPB / 32];
    if ((tid & 31) == 0) wp[tid >> 5] = (double)lsum;
    __syncthreads();
    if (tid == 0) {
        double s = 0.0;
        #pragma unroll
        for (int w = 0; w < FTPB / 32; w++) s += wp[w];
        g_partial[blockIdx.x] = s;
    }
}

__global__ void vq_finalize(int nblocks, double inv_total, float* loss_out)
{
    __shared__ double sp[256];
    const int tid = threadIdx.x;
    double s = 0.0;
    for (int i = tid; i < nblocks; i += 256) s += g_partial[i];
    sp[tid] = s;
    __syncthreads();
    for (int off = 128; off; off >>= 1) {
        if (tid < off) sp[tid] += sp[tid + off];
        __syncthreads();
    }
    if (tid == 0) {
        double mean = sp[0] * inv_total;
        loss_out[0] = (float)(mean + 0.25 * mean);
    }
}

extern "C" void kernel_launch(void* const* d_in, const int* in_sizes, int n_in,
                              void* d_out, int out_size)
{
    const float* z  = (const float*)d_in[0];
    const float* cb = (const float*)d_in[1];
    const int N = in_sizes[0] / D;
    const int K = in_sizes[1] / D;

    float* out = (float*)d_out;
    float* q_out    = out;
    float* loss_ptr = nullptr;
    float* ids_ptr  = nullptr;
    const long base = (long)N * D;
    if ((long)out_size >= base + 1 + N) { loss_ptr = out + base; ids_ptr = out + base + 1; }
    else if ((long)out_size == base + N) { ids_ptr = out + base; }
    else if ((long)out_size == base + 1) { loss_ptr = out + base; }

    int nblocks;
    if (K == KCODES && (N % MTILE) == 0 && N > 0) {
        const int ntiles = N / MTILE;
        nblocks = ntiles < GRID_MAX ? ntiles : GRID_MAX;
        cudaFuncSetAttribute(vq_mma, cudaFuncAttributeMaxDynamicSharedMemorySize, SMEM_TOTAL);
        vq_mma<<<nblocks, TPB, SMEM_TOTAL>>>(z, cb, N, q_out, ids_ptr);
    } else {
        const size_t smem_bytes = ((size_t)K * ROW_PAD + K) * sizeof(float);
        cudaFuncSetAttribute(vq_ref, cudaFuncAttributeMaxDynamicSharedMemorySize, (int)smem_bytes);
        nblocks = (N + FTPB - 1) / FTPB;
        vq_ref<<<nblocks, FTPB, smem_bytes>>>(z, cb, N, K, q_out, ids_ptr);
    }

    if (loss_ptr) {
        double inv_total = 1.0 / ((double)N * (double)D);
        vq_finalize<<<1, 256>>>(nblocks, inv_total, loss_ptr);
    }
}